// round 3
// baseline (speedup 1.0000x reference)
#include <cuda_runtime.h>
#include <cuda_bf16.h>

#define MAXN 100000
#define MAXE 1600000
#define F 64

// ---------------- scratch (static device globals; no allocation) -------------
__device__ int    d_is64;                // 1 if edge_index is int64, 0 if int32
__device__ int    d_counts[MAXN];        // degree counts (incl. self loop)
__device__ int    d_rowptr[MAXN + 1];    // CSR row pointers (by destination)
__device__ int    d_cursor[MAXN];        // scatter cursors
__device__ float  d_dinv[MAXN];          // deg^-1/2
__device__ int    d_blocksums[512];      // scan partials
__device__ float2 d_edges[MAXE + MAXN];  // packed {src_as_float_bits, norm}
__device__ float  d_h[MAXN * F];         // GEMM output buffer
__device__ float  d_g[MAXN * F];         // layer-1 activation buffer

// ---------------- edge index accessors ---------------------------------------
__device__ __forceinline__ int edge_at(const void* ei, long long idx) {
    if (d_is64) return (int)((const long long*)ei)[idx];
    return ((const int*)ei)[idx];
}

// Detect dtype: if int64 with values < 2^31, every odd 32-bit word is zero.
__global__ void k_detect(const unsigned int* __restrict__ p) {
    bool allz = true;
    for (int i = threadIdx.x * 2 + 1; i < 256; i += 64) {
        if (p[i] != 0u) allz = false;
    }
    unsigned int m = __ballot_sync(0xffffffffu, allz);
    if (threadIdx.x == 0) d_is64 = (m == 0xffffffffu) ? 1 : 0;
}

// ---------------- graph build ------------------------------------------------
__global__ void k_init_counts(int n) {
    int i = blockIdx.x * blockDim.x + threadIdx.x;
    if (i < n) d_counts[i] = 1;  // self loop
}

__global__ void k_hist(const void* __restrict__ ei, int E) {
    int e = blockIdx.x * blockDim.x + threadIdx.x;
    if (e < E) {
        int c = edge_at(ei, (long long)E + e);  // col = edge_index[1]
        atomicAdd(&d_counts[c], 1);
    }
}

__global__ void k_dinv(int n) {
    int i = blockIdx.x * blockDim.x + threadIdx.x;
    if (i < n) d_dinv[i] = rsqrtf((float)d_counts[i]);
}

// exclusive scan of d_counts -> d_rowptr (3-phase)
__global__ void k_scanA(int n) {  // 512 threads/block, 1 item/thread
    int i = blockIdx.x * 512 + threadIdx.x;
    int lane = threadIdx.x & 31;
    int v = (i < n) ? d_counts[i] : 0;
    int x = v;
    #pragma unroll
    for (int d = 1; d < 32; d <<= 1) {
        int y = __shfl_up_sync(0xffffffffu, x, d);
        if (lane >= d) x += y;
    }
    __shared__ int ws[16];
    if (lane == 31) ws[threadIdx.x >> 5] = x;
    __syncthreads();
    if (threadIdx.x < 16) {
        int z = ws[threadIdx.x];
        #pragma unroll
        for (int d = 1; d < 16; d <<= 1) {
            int y = __shfl_up_sync(0xffffu, z, d);
            if ((int)threadIdx.x >= d) z += y;
        }
        ws[threadIdx.x] = z;
    }
    __syncthreads();
    int off = (threadIdx.x >= 32) ? ws[(threadIdx.x >> 5) - 1] : 0;
    int incl = x + off;
    if (i < n) d_rowptr[i] = incl - v;  // block-local exclusive
    if (threadIdx.x == 511) d_blocksums[blockIdx.x] = incl;
}

__global__ void k_scanB(int nb) {  // single block, 256 threads
    int t = threadIdx.x;
    int lane = t & 31;
    int v = (t < nb) ? d_blocksums[t] : 0;
    int x = v;
    #pragma unroll
    for (int d = 1; d < 32; d <<= 1) {
        int y = __shfl_up_sync(0xffffffffu, x, d);
        if (lane >= d) x += y;
    }
    __shared__ int ws[8];
    if (lane == 31) ws[t >> 5] = x;
    __syncthreads();
    if (t < 8) {
        int z = ws[t];
        #pragma unroll
        for (int d = 1; d < 8; d <<= 1) {
            int y = __shfl_up_sync(0xffu, z, d);
            if (t >= d) z += y;
        }
        ws[t] = z;
    }
    __syncthreads();
    int off = (t >= 32) ? ws[(t >> 5) - 1] : 0;
    if (t < nb) d_blocksums[t] = (x + off) - v;  // exclusive
}

__global__ void k_scanC(int n, int total) {
    int i = blockIdx.x * blockDim.x + threadIdx.x;
    if (i < n) {
        int r = d_rowptr[i] + d_blocksums[i >> 9];
        d_rowptr[i] = r;
        d_cursor[i] = r;
    }
    if (i == 0) d_rowptr[n] = total;
}

__global__ void k_scatter(const void* __restrict__ ei, int E, int n) {
    int idx = blockIdx.x * blockDim.x + threadIdx.x;
    if (idx < E) {
        int r = edge_at(ei, idx);                  // row = edge_index[0]
        int c = edge_at(ei, (long long)E + idx);   // col = edge_index[1]
        float nm = d_dinv[r] * d_dinv[c];
        int pos = atomicAdd(&d_cursor[c], 1);
        d_edges[pos] = make_float2(__int_as_float(r), nm);
    } else if (idx < E + n) {
        int i = idx - E;
        float di = d_dinv[i];
        int pos = atomicAdd(&d_cursor[i], 1);
        d_edges[pos] = make_float2(__int_as_float(i), di * di);
    }
}

// ---------------- GEMM: d_h[n,64] = SRC[n,64] @ W[64,64] ---------------------
// SRC = X param (layer 1) or d_g global (layer 2). 128 threads/block,
// 64 nodes/block; thread computes 8 nodes x 4 features.
template <bool FIRST>
__global__ __launch_bounds__(128) void k_gemm(const float* __restrict__ X,
                                              const float* __restrict__ W, int n) {
    __shared__ float4 Ws[64 * 16];  // [k][f4]
    __shared__ float4 Xs[64 * 16];  // [node][k4]
    const float* src = FIRST ? X : (const float*)d_g;
    int t = threadIdx.x;
    int base = blockIdx.x * 64;
    for (int i = t; i < 1024; i += 128) Ws[i] = ((const float4*)W)[i];
    for (int i = t; i < 1024; i += 128) {
        int node = i >> 4, k4 = i & 15;
        float4 v = make_float4(0.f, 0.f, 0.f, 0.f);
        if (base + node < n) v = ((const float4*)src)[(base + node) * 16 + k4];
        Xs[i] = v;
    }
    __syncthreads();
    int fg = t & 15;   // feature group (4 feats)
    int ng = t >> 4;   // node group (8 nodes)
    float4 acc[8];
    #pragma unroll
    for (int j = 0; j < 8; j++) acc[j] = make_float4(0.f, 0.f, 0.f, 0.f);
    #pragma unroll
    for (int k4 = 0; k4 < 16; k4++) {
        float4 w0 = Ws[(k4 * 4 + 0) * 16 + fg];
        float4 w1 = Ws[(k4 * 4 + 1) * 16 + fg];
        float4 w2 = Ws[(k4 * 4 + 2) * 16 + fg];
        float4 w3 = Ws[(k4 * 4 + 3) * 16 + fg];
        #pragma unroll
        for (int j = 0; j < 8; j++) {
            float4 xv = Xs[(ng * 8 + j) * 16 + k4];
            acc[j].x += xv.x * w0.x + xv.y * w1.x + xv.z * w2.x + xv.w * w3.x;
            acc[j].y += xv.x * w0.y + xv.y * w1.y + xv.z * w2.y + xv.w * w3.y;
            acc[j].z += xv.x * w0.z + xv.y * w1.z + xv.z * w2.z + xv.w * w3.z;
            acc[j].w += xv.x * w0.w + xv.y * w1.w + xv.z * w2.w + xv.w * w3.w;
        }
    }
    #pragma unroll
    for (int j = 0; j < 8; j++) {
        int node = base + ng * 8 + j;
        if (node < n) ((float4*)d_h)[node * 16 + fg] = acc[j];
    }
}

// ---------------- aggregation: DST[c] = sum_{e: col=c} norm_e * d_h[src_e] + b
// warp per node, float2 per lane (feats 2*lane, 2*lane+1).
// RELU=true: DST = d_g (layer 1). RELU=false: DST = OUT param (layer 2).
template <bool RELU>
__global__ void k_agg(const float* __restrict__ bias, float* __restrict__ OUT,
                      int n) {
    int gwarp = (blockIdx.x * blockDim.x + threadIdx.x) >> 5;
    if (gwarp >= n) return;
    int lane = threadIdx.x & 31;
    int s = d_rowptr[gwarp];
    int e = d_rowptr[gwarp + 1];
    const float2* H2 = (const float2*)d_h;
    float ax = 0.f, ay = 0.f;
    int j = s;
    for (; j + 1 < e; j += 2) {
        float2 e0 = d_edges[j];
        float2 e1 = d_edges[j + 1];
        int s0 = __float_as_int(e0.x);
        int s1 = __float_as_int(e1.x);
        float2 h0 = H2[s0 * 32 + lane];
        float2 h1 = H2[s1 * 32 + lane];
        ax += e0.y * h0.x + e1.y * h1.x;
        ay += e0.y * h0.y + e1.y * h1.y;
    }
    if (j < e) {
        float2 e0 = d_edges[j];
        int s0 = __float_as_int(e0.x);
        float2 h0 = H2[s0 * 32 + lane];
        ax += e0.y * h0.x;
        ay += e0.y * h0.y;
    }
    float2 bb = ((const float2*)bias)[lane];
    ax += bb.x;
    ay += bb.y;
    if (RELU) { ax = fmaxf(ax, 0.f); ay = fmaxf(ay, 0.f); }
    float2* dst = RELU ? (float2*)d_g : (float2*)OUT;
    dst[gwarp * 32 + lane] = make_float2(ax, ay);
}

// ---------------- launch -----------------------------------------------------
extern "C" void kernel_launch(void* const* d_in, const int* in_sizes, int n_in,
                              void* d_out, int out_size) {
    const float* x = (const float*)d_in[0];
    const void* ei = d_in[1];
    const float* W1 = (const float*)d_in[2];
    const float* b1 = (const float*)d_in[3];
    const float* W2 = (const float*)d_in[4];
    const float* b2 = (const float*)d_in[5];
    float* out = (float*)d_out;

    int N = in_sizes[0] / F;          // 100000
    int E = in_sizes[1] / 2;          // 1600000

    int nbA = (N + 511) / 512;

    // dtype detection + graph build
    k_detect<<<1, 64>>>((const unsigned int*)ei);
    k_init_counts<<<(N + 255) / 256, 256>>>(N);
    k_hist<<<(E + 255) / 256, 256>>>(ei, E);
    k_dinv<<<(N + 255) / 256, 256>>>(N);
    k_scanA<<<nbA, 512>>>(N);
    k_scanB<<<1, 256>>>(nbA);
    k_scanC<<<(N + 255) / 256, 256>>>(N, E + N);
    k_scatter<<<(E + N + 255) / 256, 256>>>(ei, E, N);

    // layer 1: d_h = x@W1 ; d_g = relu(agg(d_h) + b1)
    k_gemm<true><<<(N + 63) / 64, 128>>>(x, W1, N);
    k_agg<true><<<(N * 32 + 255) / 256, 256>>>(b1, out /*unused*/, N);

    // layer 2: d_h = d_g@W2 ; out = agg(d_h) + b2
    k_gemm<false><<<(N + 63) / 64, 128>>>(x /*unused*/, W2, N);
    k_agg<false><<<(N * 32 + 255) / 256, 256>>>(b2, out, N);
}